// round 1
// baseline (speedup 1.0000x reference)
#include <cuda_runtime.h>
#include <cuda_bf16.h>

// Problem constants
#define BB 32
#define NN 512
#define DD 512
#define EE 8
#define PP 96
#define KK 25
#define HH 4
#define DK 128
#define EH 32       // E*H
#define PADC 12
#define NTOK (BB*NN)            // 16384
#define MAXTILES ((NTOK/64)+EE) // 264
#define MAXTOK (MAXTILES*64)    // 16896

// ---------------- scratch (device globals; no allocation allowed) -------------
__device__ float g_q[EE*DD];            // router projected queries [E][D]
__device__ float g_qk[EH*DD];           // folded q*Wk  [eh][d]
__device__ float g_qb[EH];              // folded q*bk
__device__ float g_S[BB*EH*NN];         // scores -> softmax A, [b][eh][n]
__device__ float g_xA[BB*EH*DD];        // A^T x, [b][eh][d]
__device__ float g_attraw[BB*EE*DD];    // pre-Wo attention output [b][e][d]
__device__ float g_att[BB*EE*DD];       // post-Wo [b][e][d]
__device__ float g_invna[BB*EE];        // 1/||att||
__device__ float g_attTerm[BB*EE*PP];   // z-channel contribution + beff
__device__ float g_Weff[EE*2*DD*PP];    // folded conv*linear [e][c][d][p]
__device__ float g_beff[EE*PP];
__device__ int   g_idx[NTOK];           // selected expert per token
__device__ int   g_cnt[EE];
__device__ int   g_cursor[EE];
__device__ int   g_tokenList[MAXTOK];

// ---------------- K0: q = router @ Wq + bq ; zero counters --------------------
__global__ void k_q(const float* __restrict__ router, const float* __restrict__ Wq,
                    const float* __restrict__ bq) {
    int t = blockIdx.x * 128 + threadIdx.x;   // 4096 outputs
    int e = t >> 9, col = t & 511;
    float acc = bq[col];
    #pragma unroll 4
    for (int d = 0; d < DD; d++)
        acc += router[e*DD + d] * Wq[d*DD + col];
    g_q[t] = acc;
    if (t < EE) g_cnt[t] = 0;
}

// ---------------- K0b: qk[eh][d] = sum_j q[e,h*128+j] * Wk[d, h*128+j] -------
__global__ void k_qk(const float* __restrict__ Wk, const float* __restrict__ bk) {
    int eh = blockIdx.x;         // 32 blocks
    int e = eh >> 2, h = eh & 3;
    __shared__ float qs[DK];
    int tid = threadIdx.x;       // 512
    if (tid < DK) qs[tid] = g_q[e*DD + h*DK + tid];
    __syncthreads();
    int d = tid;
    const float* Wr = Wk + d*DD + h*DK;
    float acc = 0.f;
    #pragma unroll 8
    for (int j = 0; j < DK; j++) acc += qs[j] * Wr[j];
    g_qk[eh*DD + d] = acc;
    if (tid == 0) {
        float qb = 0.f;
        for (int j = 0; j < DK; j++) qb += qs[j] * bk[h*DK + j];
        g_qb[eh] = qb;
    }
}

// ---------------- K0c: Weff[e][c][d][p] = sum_k Wc[e,c,k]*Wp[e, d+PAD-k, p] ---
__global__ void k_weff(const float* __restrict__ Wc, const float* __restrict__ Wp) {
    int t = blockIdx.x * 256 + threadIdx.x;   // 786432 outputs
    int p = t % PP;
    int r = t / PP;
    int d = r & 511;
    int ec = r >> 9;       // e*2+c
    int e = ec >> 1;
    float acc = 0.f;
    #pragma unroll
    for (int k = 0; k < KK; k++) {
        int l = d + PADC - k;
        if (l >= 0 && l < DD)
            acc += Wc[ec*KK + k] * Wp[(e*DD + l)*PP + p];
    }
    g_Weff[t] = acc;
}

// ---------------- K0d: beff[e][p] = bc[e]*sum_l Wp[e,l,p] + bp[e,p] -----------
__global__ void k_beff(const float* __restrict__ Wp, const float* __restrict__ bc,
                       const float* __restrict__ bp) {
    int e = blockIdx.x, p = threadIdx.x;  // 8 x 96
    float s = 0.f;
    #pragma unroll 4
    for (int l = 0; l < DD; l++) s += Wp[(e*DD + l)*PP + p];
    g_beff[e*PP + p] = bc[e]*s + bp[e*PP + p];
}

// ---------------- K1: scores S[b][eh][n] = x[b,n] . qk[eh] + qb ---------------
__global__ void k_scores(const float* __restrict__ x) {
    int b = blockIdx.y;
    int n0 = blockIdx.x * 64;
    __shared__ float xs[64][65];
    __shared__ float qs[32][64];
    int tid = threadIdx.x;
    int tok = tid & 63;
    int ehBase = (tid >> 6) * 8;
    float acc[8] = {0,0,0,0,0,0,0,0};
    const float* xb = x + (b*NN + n0)*DD;
    for (int dc = 0; dc < DD; dc += 64) {
        __syncthreads();
        #pragma unroll
        for (int i = 0; i < 16; i++) {
            int idx = tid + i*256; int r = idx >> 6, c = idx & 63;
            xs[r][c] = xb[r*DD + dc + c];
        }
        #pragma unroll
        for (int i = 0; i < 8; i++) {
            int idx = tid + i*256; int r = idx >> 6, c = idx & 63;
            qs[r][c] = g_qk[r*DD + dc + c];
        }
        __syncthreads();
        #pragma unroll 8
        for (int dd = 0; dd < 64; dd++) {
            float xv = xs[tok][dd];
            #pragma unroll
            for (int j = 0; j < 8; j++)
                acc[j] += xv * qs[ehBase + j][dd];
        }
    }
    #pragma unroll
    for (int j = 0; j < 8; j++)
        g_S[(b*EH + ehBase + j)*NN + n0 + tok] = acc[j] + g_qb[ehBase + j];
}

// ---------------- K2: softmax over n per (b,eh) row (in place) ----------------
__global__ void k_softmax() {
    int row = blockIdx.x;          // 1024
    float* S = g_S + row*NN;
    __shared__ float red[256];
    int tid = threadIdx.x;
    const float scale = 0.0883883476483184405f;   // 1/sqrt(128)
    float v0 = S[tid] * scale, v1 = S[tid + 256] * scale;
    red[tid] = fmaxf(v0, v1);
    __syncthreads();
    for (int s = 128; s > 0; s >>= 1) {
        if (tid < s) red[tid] = fmaxf(red[tid], red[tid + s]);
        __syncthreads();
    }
    float m = red[0];
    __syncthreads();
    float e0 = __expf(v0 - m), e1 = __expf(v1 - m);
    red[tid] = e0 + e1;
    __syncthreads();
    for (int s = 128; s > 0; s >>= 1) {
        if (tid < s) red[tid] += red[tid + s];
        __syncthreads();
    }
    float inv = 1.0f / red[0];
    S[tid] = e0 * inv;
    S[tid + 256] = e1 * inv;
}

// ---------------- K3: xA[b][eh][d] = sum_n A[b][eh][n] * x[b][n][d] -----------
__global__ void k_xA(const float* __restrict__ x) {
    int b = blockIdx.y;
    int d0 = blockIdx.x * 64;
    __shared__ float As[32][64];
    __shared__ float xs[64][65];
    int tid = threadIdx.x;
    int dcol = tid & 63;
    int ehBase = (tid >> 6) * 8;
    float acc[8] = {0,0,0,0,0,0,0,0};
    for (int nc = 0; nc < NN; nc += 64) {
        __syncthreads();
        #pragma unroll
        for (int i = 0; i < 8; i++) {
            int idx = tid + i*256; int r = idx >> 6, c = idx & 63;
            As[r][c] = g_S[(b*EH + r)*NN + nc + c];
        }
        #pragma unroll
        for (int i = 0; i < 16; i++) {
            int idx = tid + i*256; int r = idx >> 6, c = idx & 63;
            xs[r][c] = x[(b*NN + nc + r)*DD + d0 + c];
        }
        __syncthreads();
        #pragma unroll 8
        for (int nn = 0; nn < 64; nn++) {
            float xv = xs[nn][dcol];
            #pragma unroll
            for (int j = 0; j < 8; j++)
                acc[j] += As[ehBase + j][nn] * xv;
        }
    }
    #pragma unroll
    for (int j = 0; j < 8; j++)
        g_xA[(b*EH + ehBase + j)*DD + d0 + dcol] = acc[j];
}

// ---------------- K4: attraw[b][e][col] = xA[b][e*4+h] . Wv[:,col] + bv -------
__global__ void k_attraw(const float* __restrict__ Wv, const float* __restrict__ bv) {
    int e = blockIdx.x, bp = blockIdx.y;   // (8,16)
    int col = threadIdx.x;                 // 512
    int h = col >> 7;
    int b0 = 2*bp;
    const float* r0 = g_xA + (b0*EH + e*4 + h)*DD;
    const float* r1 = g_xA + ((b0+1)*EH + e*4 + h)*DD;
    float a0 = bv[col], a1 = a0;
    #pragma unroll 4
    for (int d = 0; d < DD; d++) {
        float w = Wv[d*DD + col];
        a0 += r0[d]*w; a1 += r1[d]*w;
    }
    g_attraw[(b0*EE + e)*DD + col] = a0;
    g_attraw[((b0+1)*EE + e)*DD + col] = a1;
}

// ---------------- K5: att = attraw @ Wo + bo ----------------------------------
__global__ void k_wo(const float* __restrict__ Wo, const float* __restrict__ bo) {
    int e = blockIdx.x, bp = blockIdx.y;
    int col = threadIdx.x;
    int b0 = 2*bp;
    const float* r0 = g_attraw + (b0*EE + e)*DD;
    const float* r1 = g_attraw + ((b0+1)*EE + e)*DD;
    float a0 = bo[col], a1 = a0;
    #pragma unroll 4
    for (int d = 0; d < DD; d++) {
        float w = Wo[d*DD + col];
        a0 += r0[d]*w; a1 += r1[d]*w;
    }
    g_att[(b0*EE + e)*DD + col] = a0;
    g_att[((b0+1)*EE + e)*DD + col] = a1;
}

// -------- K6: inv norm of att rows + attTerm[b][e][p] = att.WeffZ + beff ------
__global__ void k_nat() {
    int be = blockIdx.x;       // 256
    int e = be & 7;
    __shared__ float atts[DD];
    __shared__ float red[128];
    int tid = threadIdx.x;     // 128
    float ss = 0.f;
    for (int i = tid; i < DD; i += 128) {
        float v = g_att[be*DD + i];
        atts[i] = v; ss += v*v;
    }
    red[tid] = ss;
    __syncthreads();
    for (int s = 64; s > 0; s >>= 1) {
        if (tid < s) red[tid] += red[tid + s];
        __syncthreads();
    }
    if (tid == 0) g_invna[be] = rsqrtf(red[0]);
    if (tid < PP) {
        float acc = g_beff[e*PP + tid];
        const float* W = g_Weff + ((e*2 + 1)*DD)*PP + tid;
        #pragma unroll 4
        for (int d = 0; d < DD; d++) acc += atts[d] * W[d*PP];
        g_attTerm[be*PP + tid] = acc;
    }
}

// -------- K7: route: idx[b,n] = argmax_e (att[b,e].x[b,n]) * invna[b,e] -------
__global__ void k_route(const float* __restrict__ x) {
    int b = blockIdx.y;
    int n0 = blockIdx.x * 64;
    __shared__ float atts[EE][DD];
    __shared__ float innv[EE];
    int tid = threadIdx.x;    // 256
    for (int i = tid; i < EE*DD; i += 256)
        atts[i >> 9][i & 511] = g_att[b*EE*DD + i];
    if (tid < EE) innv[tid] = g_invna[b*EE + tid];
    __syncthreads();
    int warp = tid >> 5, lane = tid & 31;
    for (int t = warp; t < 64; t += 8) {
        int n = n0 + t;
        const float* xr = x + (b*NN + n)*DD;
        float acc[8] = {0,0,0,0,0,0,0,0};
        for (int d = lane; d < DD; d += 32) {
            float xv = xr[d];
            #pragma unroll
            for (int j = 0; j < 8; j++) acc[j] += atts[j][d] * xv;
        }
        #pragma unroll
        for (int j = 0; j < 8; j++)
            for (int off = 16; off; off >>= 1)
                acc[j] += __shfl_xor_sync(0xffffffff, acc[j], off);
        if (lane == 0) {
            int best = 0; float bs = acc[0]*innv[0];
            #pragma unroll
            for (int j = 1; j < 8; j++) {
                float s = acc[j]*innv[j];
                if (s > bs) { bs = s; best = j; }   // strict > keeps first max (JAX tie rule)
            }
            g_idx[b*NN + n] = best;
            atomicAdd(&g_cnt[best], 1);
        }
    }
}

// -------- K8: bucket offsets (64-aligned) + prefill token list ---------------
__global__ void k_offsets() {
    int tid = threadIdx.x;
    if (tid == 0) {
        int s = 0;
        for (int e = 0; e < EE; e++) {
            g_cursor[e] = s;
            s += ((g_cnt[e] + 63) >> 6) << 6;
        }
    }
    for (int i = tid; i < MAXTOK; i += 256) g_tokenList[i] = -1;
}

// -------- K9: scatter tokens into expert buckets ------------------------------
__global__ void k_scatter() {
    int t = blockIdx.x * 256 + threadIdx.x;   // 16384
    int e = g_idx[t];
    int pos = atomicAdd(&g_cursor[e], 1);
    g_tokenList[pos] = t;
}

// -------- K10: grouped GEMM: out[t,p] = x[t].WeffX[e] + attTerm[b,e,p] --------
__global__ void k_final(const float* __restrict__ x, float* __restrict__ out) {
    int tile = blockIdx.x;     // 264
    __shared__ int gtok[64];
    __shared__ float xs[64][65];
    __shared__ float ws[64][97];
    int tid = threadIdx.x;     // 256
    if (tid < 64) gtok[tid] = g_tokenList[tile*64 + tid];
    __syncthreads();
    int e = -1;
    for (int i = 0; i < 64; i++)
        if (gtok[i] >= 0) { e = g_idx[gtok[i]]; break; }
    if (e < 0) return;       // fully-dummy tile (uniform across block)

    int pg = tid & 15;       // 16 p-groups of 6
    int tg = tid >> 4;       // 16 tok-groups of 4
    int p0 = pg * 6, t0 = tg * 4;
    float acc[4][6];
    #pragma unroll
    for (int i = 0; i < 4; i++)
        #pragma unroll
        for (int j = 0; j < 6; j++) acc[i][j] = 0.f;

    const float* We = g_Weff + (e*2 + 0)*DD*PP;   // x-channel
    for (int dc = 0; dc < DD; dc += 64) {
        __syncthreads();
        #pragma unroll
        for (int i = 0; i < 16; i++) {
            int idx = tid + i*256; int r = idx >> 6, c = idx & 63;
            int t = gtok[r];
            xs[r][c] = (t >= 0) ? x[t*DD + dc + c] : 0.0f;
        }
        #pragma unroll
        for (int i = 0; i < 24; i++) {
            int idx = tid + i*256;
            int r = idx / 96, c = idx - r*96;
            ws[r][c] = We[(dc + r)*PP + c];
        }
        __syncthreads();
        #pragma unroll 4
        for (int dd = 0; dd < 64; dd++) {
            float xv[4], wv[6];
            #pragma unroll
            for (int i = 0; i < 4; i++) xv[i] = xs[t0 + i][dd];
            #pragma unroll
            for (int j = 0; j < 6; j++) wv[j] = ws[dd][p0 + j];
            #pragma unroll
            for (int i = 0; i < 4; i++)
                #pragma unroll
                for (int j = 0; j < 6; j++)
                    acc[i][j] += xv[i] * wv[j];
        }
    }
    #pragma unroll
    for (int i = 0; i < 4; i++) {
        int t = gtok[t0 + i];
        if (t < 0) continue;
        int b = t >> 9;
        const float* at = g_attTerm + (b*EE + e)*PP;
        #pragma unroll
        for (int j = 0; j < 6; j++)
            out[t*PP + p0 + j] = acc[i][j] + at[p0 + j];
    }
}

// ------------------------------------------------------------------------------
extern "C" void kernel_launch(void* const* d_in, const int* in_sizes, int n_in,
                              void* d_out, int out_size) {
    const float* x      = (const float*)d_in[0];
    const float* router = (const float*)d_in[1];
    const float* Wq     = (const float*)d_in[2];
    const float* bq     = (const float*)d_in[3];
    const float* Wk     = (const float*)d_in[4];
    const float* bk     = (const float*)d_in[5];
    const float* Wv     = (const float*)d_in[6];
    const float* bv     = (const float*)d_in[7];
    const float* Wo     = (const float*)d_in[8];
    const float* bo     = (const float*)d_in[9];
    const float* Wc     = (const float*)d_in[10];
    const float* bc     = (const float*)d_in[11];
    const float* Wp     = (const float*)d_in[12];
    const float* bp     = (const float*)d_in[13];
    float* out = (float*)d_out;

    k_q      <<<32, 128>>>(router, Wq, bq);
    k_qk     <<<32, 512>>>(Wk, bk);
    k_weff   <<<3072, 256>>>(Wc, Wp);
    k_beff   <<<8, 96>>>(Wp, bc, bp);
    k_scores <<<dim3(8, 32), 256>>>(x);
    k_softmax<<<BB*EH, 256>>>();
    k_xA     <<<dim3(8, 32), 256>>>(x);
    k_attraw <<<dim3(8, 16), 512>>>(Wv, bv);
    k_wo     <<<dim3(8, 16), 512>>>(Wo, bo);
    k_nat    <<<BB*EE, 128>>>();
    k_route  <<<dim3(8, 32), 256>>>(x);
    k_offsets<<<1, 256>>>();
    k_scatter<<<64, 256>>>();
    k_final  <<<MAXTILES, 256>>>(x, out);
}